// round 9
// baseline (speedup 1.0000x reference)
#include <cuda_runtime.h>

#define BB 2
#define NN 1024
#define DD 3
#define F1 32
#define F2 64
#define NTH 1024
#define NB 256
#define GRID 128

// Scratch (no allocs allowed). Point-major layouts: [batch][point][feature]
__device__ float g_h1[BB*NN*F1];
__device__ float g_h2[BB*NN*F2];
__device__ float g_Hsum[BB*F2];
__device__ unsigned g_bar_count = 0;
__device__ unsigned g_bar_gen = 0;

// L2-coherent loads for same-launch cross-block data (NEVER __ldg here).
__device__ __forceinline__ float ldcg(const float* p) {
    float v;
    asm volatile("ld.global.cg.f32 %0, [%1];" : "=f"(v) : "l"(p));
    return v;
}
__device__ __forceinline__ float4 ldcg4(const float* p) {
    float4 v;
    asm volatile("ld.global.cg.v4.f32 {%0,%1,%2,%3}, [%4];"
                 : "=f"(v.x), "=f"(v.y), "=f"(v.z), "=f"(v.w) : "l"(p));
    return v;
}

// ---------------------------------------------------------------------------
// Software grid barrier (all GRID blocks co-resident: GRID <= 148 SMs)
// ---------------------------------------------------------------------------
__device__ __forceinline__ void grid_sync()
{
    __syncthreads();
    if (threadIdx.x == 0) {
        __threadfence();
        unsigned gen = atomicAdd(&g_bar_gen, 0u);
        unsigned arrived = atomicAdd(&g_bar_count, 1u) + 1u;
        if (arrived == GRID) {
            g_bar_count = 0u;
            __threadfence();
            atomicAdd(&g_bar_gen, 1u);
        } else {
            while (atomicAdd(&g_bar_gen, 0u) == gen) { }
        }
    }
    __syncthreads();
}

// ---------------------------------------------------------------------------
// Rank engine: 1024 values, ONE per thread. cnt/sum of {c_j > q} via 256-bin
// histogram (smem atomics), bin-level count+sum exclusive scan, counting-sort
// scatter, short partial-bin scan per query. Ties contribute a+c==0: free.
// ---------------------------------------------------------------------------
struct RankSmem {
    int   cnt[NB];
    int   cur[NB];
    float bsum[NB];
    int   E[NB+1];
    float SS[NB+1];
    float sc[NN];
    float redA[32];
    float redB[32];
    float w3s[2*F2*DD];
    float Ssh[DD];
};

__device__ void rank_build(RankSmem* S, float c, int t,
                           float& mn_out, float& invw_out)
{
    int lane = t & 31, w = t >> 5;

    if (t < NB) S->cnt[t] = 0;
    else if (t < 2*NB) S->bsum[t - NB] = 0.0f;

    // block min/max of c
    float mnl = c, mxl = c;
#pragma unroll
    for (int o = 16; o > 0; o >>= 1) {
        mnl = fminf(mnl, __shfl_xor_sync(0xffffffffu, mnl, o));
        mxl = fmaxf(mxl, __shfl_xor_sync(0xffffffffu, mxl, o));
    }
    if (lane == 0) { S->redA[w] = mnl; S->redB[w] = mxl; }
    __syncthreads();
    if (t < 32) {
        mnl = S->redA[t]; mxl = S->redB[t];
#pragma unroll
        for (int o = 16; o > 0; o >>= 1) {
            mnl = fminf(mnl, __shfl_xor_sync(0xffffffffu, mnl, o));
            mxl = fmaxf(mxl, __shfl_xor_sync(0xffffffffu, mxl, o));
        }
        if (t == 0) { S->redA[0] = mnl; S->redB[0] = (float)NB / fmaxf(mxl - mnl, 1e-30f); }
    }
    __syncthreads();
    float mn = S->redA[0], invw = S->redB[0];
    mn_out = mn; invw_out = invw;

    int b = min(max((int)((c - mn) * invw), 0), NB-1);
    atomicAdd(&S->cnt[b], 1);
    atomicAdd(&S->bsum[b], c);
    __syncthreads();

    // exclusive scan over NB bins (count + sum): warps 0..7
    int v = 0; float s = 0.0f;
    int vi = 0; float si = 0.0f;
    if (t < NB) {
        v = S->cnt[t]; s = S->bsum[t];
        vi = v; si = s;
#pragma unroll
        for (int o = 1; o < 32; o <<= 1) {
            int   nv = __shfl_up_sync(0xffffffffu, vi, o);
            float ns = __shfl_up_sync(0xffffffffu, si, o);
            if (lane >= o) { vi += nv; si += ns; }
        }
        if (lane == 31) { S->redA[w] = (float)vi; S->redB[w] = si; }
    }
    __syncthreads();
    if (t < 8) {
        float v8 = S->redA[t], s8 = S->redB[t];
        float vv = v8, ss = s8;
#pragma unroll
        for (int o = 1; o < 8; o <<= 1) {
            float nv = __shfl_up_sync(0x000000ffu, vv, o);
            float ns = __shfl_up_sync(0x000000ffu, ss, o);
            if (t >= o) { vv += nv; ss += ns; }
        }
        S->redA[t] = vv - v8;
        S->redB[t] = ss - s8;
    }
    __syncthreads();
    if (t < NB) {
        int   excl  = vi - v + (int)S->redA[w];
        float exclS = si - s + S->redB[w];
        S->E[t] = excl; S->SS[t] = exclS; S->cur[t] = excl;
        if (t == NB-1) { S->E[NB] = excl + v; S->SS[NB] = exclS + s; }
    }
    __syncthreads();

    int p = atomicAdd(&S->cur[b], 1);
    S->sc[p] = c;
    __syncthreads();
}

__device__ __forceinline__ float rank_query(const RankSmem* S, float a, float cself,
                                            float mn, float invw)
{
    const float scale = 1.0f / (float)(NN - 1);
    float q = -a;
    int qb = min(max((int)((q - mn) * invw), 0), NB-1);
    int beg = S->E[qb], end = S->E[qb+1];
    float cnt = (float)(NN - end);
    float sum = S->SS[NB] - S->SS[qb+1];
    for (int k = beg; k < end; k++) {
        float v = S->sc[k];
        if (v > q) { cnt += 1.0f; sum += v; }
    }
    float self = fmaxf(a + cself, 0.0f);
    return (a * cnt + sum - self) * scale;
}

// ---------------------------------------------------------------------------
// Fused mega-kernel: stage1 -> grid_sync -> stage2 -> grid_sync -> final
// ---------------------------------------------------------------------------
__global__ __launch_bounds__(NTH) void fused_all(
    const float* __restrict__ x,
    const float* __restrict__ W1,
    const float* __restrict__ b1,
    const float* __restrict__ W2,
    const float* __restrict__ b2,
    const float* __restrict__ W3,
    const float* __restrict__ b3,
    float* __restrict__ out)
{
    __shared__ RankSmem S;
    __shared__ float wt[F1], wb[F1];

    int t = threadIdx.x;
    int blk = blockIdx.x;

    // ---------------- Phase 1: stage1, blocks 0..63, point t ----------------
    if (blk < BB*F1) {
        int b = blk >> 5;
        int f = blk & 31;
        float w0 = W1[0*F1+f], w1 = W1[1*F1+f], w2 = W1[2*F1+f];
        float w3 = W1[3*F1+f], w4 = W1[4*F1+f], w5 = W1[5*F1+f];
        float bias = b1[f];
        const float* xb = x + b*NN*DD;

        float x0 = xb[3*t+0], x1 = xb[3*t+1], x2 = xb[3*t+2];
        float a = x0*w0 + x1*w1 + x2*w2 + bias;
        float c = x0*w3 + x1*w4 + x2*w5;

        float mn, invw;
        rank_build(&S, c, t, mn, invw);

        // point-major store: h1[b][t][f]
        g_h1[(b*NN + t)*F1 + f] = rank_query(&S, a, c, mn, invw);
    }

    grid_sync();

    // ---------------- Phase 2: stage2, all 128 blocks, point t --------------
    {
        int b = blk >> 6;
        int f2 = blk & 63;
        if (t < F1) {
            wt[t] = W2[t*F2 + f2];
            wb[t] = W2[(F1 + t)*F2 + f2];
        }
        float bias = b2[f2];
        __syncthreads();

        // batched vector loads of this point's 32 h1 features
        const float* h1p = g_h1 + (size_t)(b*NN + t)*F1;
        float4 hv[8];
#pragma unroll
        for (int k = 0; k < 8; k++) hv[k] = ldcg4(h1p + 4*k);

        float a = bias, c = 0.0f;
#pragma unroll
        for (int k = 0; k < 8; k++) {
            a += hv[k].x*wt[4*k+0] + hv[k].y*wt[4*k+1] + hv[k].z*wt[4*k+2] + hv[k].w*wt[4*k+3];
            c += hv[k].x*wb[4*k+0] + hv[k].y*wb[4*k+1] + hv[k].z*wb[4*k+2] + hv[k].w*wb[4*k+3];
        }

        float mn, invw;
        rank_build(&S, c, t, mn, invw);

        float h = rank_query(&S, a, c, mn, invw);
        g_h2[(size_t)(b*NN + t)*F2 + f2] = h;

        // block-reduce h -> Hsum[b][f2]
        __syncthreads();
        int lane = t & 31, w = t >> 5;
        float hloc = h;
#pragma unroll
        for (int o = 16; o > 0; o >>= 1)
            hloc += __shfl_xor_sync(0xffffffffu, hloc, o);
        if (lane == 0) S.redA[w] = hloc;
        __syncthreads();
        if (t < 32) {
            float v = S.redA[t];
#pragma unroll
            for (int o = 16; o > 0; o >>= 1)
                v += __shfl_xor_sync(0xffffffffu, v, o);
            if (t == 0) g_Hsum[b*F2 + f2] = v;
        }
    }

    grid_sync();

    // ---------------- Phase 3: final, 16 points per block, 1/warp -----------
    {
        int pg_base = blk * 16;          // 128 * 16 = 2048
        int b = pg_base >> 10;

        for (int k = t; k < 2*F2*DD; k += NTH) S.w3s[k] = W3[k];
        __syncthreads();
        if (t < DD) {
            float acc = 0.0f;
            const float* Hs = g_Hsum + b*F2;
#pragma unroll
            for (int f = 0; f < F2; f++) acc += ldcg(&Hs[f]) * S.w3s[(F2+f)*DD + t];
            S.Ssh[t] = acc;
        }
        __syncthreads();

        int w = t >> 5, lane = t & 31;
        if (w < 16) {
            int pg = pg_base + w;
            int pi = pg & (NN - 1);
            const float* h2p = g_h2 + (size_t)(b*NN + pi)*F2;

            // coalesced within warp: lanes read consecutive features
            float hA = ldcg(&h2p[lane]);
            float hB = ldcg(&h2p[lane + 32]);
            int fA = lane, fB = lane + 32;

            float a0 = hA*S.w3s[fA*DD+0] + hB*S.w3s[fB*DD+0];
            float a1 = hA*S.w3s[fA*DD+1] + hB*S.w3s[fB*DD+1];
            float a2 = hA*S.w3s[fA*DD+2] + hB*S.w3s[fB*DD+2];
            float c0 = hA*S.w3s[(F2+fA)*DD+0] + hB*S.w3s[(F2+fB)*DD+0];
            float c1 = hA*S.w3s[(F2+fA)*DD+1] + hB*S.w3s[(F2+fB)*DD+1];
            float c2 = hA*S.w3s[(F2+fA)*DD+2] + hB*S.w3s[(F2+fB)*DD+2];

#pragma unroll
            for (int o = 16; o > 0; o >>= 1) {
                a0 += __shfl_xor_sync(0xffffffffu, a0, o);
                a1 += __shfl_xor_sync(0xffffffffu, a1, o);
                a2 += __shfl_xor_sync(0xffffffffu, a2, o);
                c0 += __shfl_xor_sync(0xffffffffu, c0, o);
                c1 += __shfl_xor_sync(0xffffffffu, c1, o);
                c2 += __shfl_xor_sync(0xffffffffu, c2, o);
            }

            if (lane == 0) {
                const float scale = 1.0f / (float)(NN - 1);
                out[pg*3+0] = a0 + b3[0] + (S.Ssh[0] - c0) * scale;
                out[pg*3+1] = a1 + b3[1] + (S.Ssh[1] - c1) * scale;
                out[pg*3+2] = a2 + b3[2] + (S.Ssh[2] - c2) * scale;
            }
        }
    }
}

// ---------------------------------------------------------------------------
extern "C" void kernel_launch(void* const* d_in, const int* in_sizes, int n_in,
                              void* d_out, int out_size)
{
    const float* x  = (const float*)d_in[0];   // (2, 3072)
    const float* W1 = (const float*)d_in[1];   // (6, 32)
    const float* b1 = (const float*)d_in[2];   // (32,)
    const float* W2 = (const float*)d_in[3];   // (64, 64)
    const float* b2 = (const float*)d_in[4];   // (64,)
    const float* W3 = (const float*)d_in[5];   // (128, 3)
    const float* b3 = (const float*)d_in[6];   // (3,)
    float* out = (float*)d_out;

    fused_all<<<GRID, NTH>>>(x, W1, b1, W2, b2, W3, b3, out);
}

// round 11
// speedup vs baseline: 1.1158x; 1.1158x over previous
#include <cuda_runtime.h>

#define BB 2
#define NN 1024
#define DD 3
#define F1 32
#define F2 64
#define NTH 512
#define NB 256
#define GRID 128

// Scratch (no allocs allowed). g_h1 point-major: [batch][point][feature]
__device__ float g_h1[BB*NN*F1];
__device__ unsigned g_bar_count = 0;
__device__ unsigned g_bar_gen = 0;

// L2-coherent loads for same-launch cross-block data (NEVER __ldg here).
__device__ __forceinline__ float4 ldcg4(const float* p) {
    float4 v;
    asm volatile("ld.global.cg.v4.f32 {%0,%1,%2,%3}, [%4];"
                 : "=f"(v.x), "=f"(v.y), "=f"(v.z), "=f"(v.w) : "l"(p));
    return v;
}
__device__ __forceinline__ unsigned ldcg_u(const unsigned* p) {
    unsigned v;
    asm volatile("ld.global.cg.u32 %0, [%1];" : "=r"(v) : "l"(p) : "memory");
    return v;
}

// ---------------------------------------------------------------------------
// Software grid barrier: arrival via one atomic per block; polling via plain
// L2 loads + nanosleep (polls don't serialize in the LTS atomic unit).
// ---------------------------------------------------------------------------
__device__ __forceinline__ void grid_sync()
{
    __syncthreads();
    if (threadIdx.x == 0) {
        __threadfence();
        unsigned gen = atomicAdd(&g_bar_gen, 0u);   // ordered read of generation
        unsigned arrived = atomicAdd(&g_bar_count, 1u) + 1u;
        if (arrived == GRID) {
            g_bar_count = 0u;
            __threadfence();
            atomicAdd(&g_bar_gen, 1u);
        } else {
            while (ldcg_u(&g_bar_gen) == gen) __nanosleep(64);
        }
        __threadfence();
    }
    __syncthreads();
}

// ---------------------------------------------------------------------------
// Rank engine: 1024 values, TWO per thread (t, t+512). cnt/sum of {c_j > q}
// via 256-bin histogram + bin-level count/sum scan + counting-sort scatter.
// Ties contribute a+c==0: boundary-free.
// ---------------------------------------------------------------------------
struct RankSmem {
    int   cnt[NB];
    int   cur[NB];
    float bsum[NB];
    int   E[NB+1];
    float SS[NB+1];
    float sc[NN];
    float redA[16];
    float redB[16];
};

__device__ void rank_build(RankSmem* S, float c0, float c1, int t,
                           float& mn_out, float& invw_out)
{
    int lane = t & 31, w = t >> 5;

    if (t < NB) S->cnt[t] = 0;
    else S->bsum[t - NB] = 0.0f;

    // block min/max of c
    float mnl = fminf(c0, c1), mxl = fmaxf(c0, c1);
#pragma unroll
    for (int o = 16; o > 0; o >>= 1) {
        mnl = fminf(mnl, __shfl_xor_sync(0xffffffffu, mnl, o));
        mxl = fmaxf(mxl, __shfl_xor_sync(0xffffffffu, mxl, o));
    }
    if (lane == 0) { S->redA[w] = mnl; S->redB[w] = mxl; }
    __syncthreads();
    if (t < 16) {
        mnl = S->redA[t]; mxl = S->redB[t];
#pragma unroll
        for (int o = 8; o > 0; o >>= 1) {
            mnl = fminf(mnl, __shfl_xor_sync(0x0000ffffu, mnl, o));
            mxl = fmaxf(mxl, __shfl_xor_sync(0x0000ffffu, mxl, o));
        }
        if (t == 0) { S->redA[0] = mnl; S->redB[0] = (float)NB / fmaxf(mxl - mnl, 1e-30f); }
    }
    __syncthreads();
    float mn = S->redA[0], invw = S->redB[0];
    mn_out = mn; invw_out = invw;

    int b0 = min(max((int)((c0 - mn) * invw), 0), NB-1);
    int b1 = min(max((int)((c1 - mn) * invw), 0), NB-1);
    atomicAdd(&S->cnt[b0], 1);  atomicAdd(&S->bsum[b0], c0);
    atomicAdd(&S->cnt[b1], 1);  atomicAdd(&S->bsum[b1], c1);
    __syncthreads();

    // exclusive scan over NB bins (count + sum): warps 0..7
    int v = 0; float s = 0.0f;
    int vi = 0; float si = 0.0f;
    if (t < NB) {
        v = S->cnt[t]; s = S->bsum[t];
        vi = v; si = s;
#pragma unroll
        for (int o = 1; o < 32; o <<= 1) {
            int   nv = __shfl_up_sync(0xffffffffu, vi, o);
            float ns = __shfl_up_sync(0xffffffffu, si, o);
            if (lane >= o) { vi += nv; si += ns; }
        }
        if (lane == 31) { S->redA[w] = (float)vi; S->redB[w] = si; }
    }
    __syncthreads();
    if (t < 8) {
        float v8 = S->redA[t], s8 = S->redB[t];
        float vv = v8, ss = s8;
#pragma unroll
        for (int o = 1; o < 8; o <<= 1) {
            float nv = __shfl_up_sync(0x000000ffu, vv, o);
            float ns = __shfl_up_sync(0x000000ffu, ss, o);
            if (t >= o) { vv += nv; ss += ns; }
        }
        S->redA[t] = vv - v8;
        S->redB[t] = ss - s8;
    }
    __syncthreads();
    if (t < NB) {
        int   excl  = vi - v + (int)S->redA[w];
        float exclS = si - s + S->redB[w];
        S->E[t] = excl; S->SS[t] = exclS; S->cur[t] = excl;
        if (t == NB-1) { S->E[NB] = excl + v; S->SS[NB] = exclS + s; }
    }
    __syncthreads();

    int p0 = atomicAdd(&S->cur[b0], 1);  S->sc[p0] = c0;
    int p1 = atomicAdd(&S->cur[b1], 1);  S->sc[p1] = c1;
    __syncthreads();
}

__device__ __forceinline__ float rank_query(const RankSmem* S, float a, float cself,
                                            float mn, float invw)
{
    const float scale = 1.0f / (float)(NN - 1);
    float q = -a;
    int qb = min(max((int)((q - mn) * invw), 0), NB-1);
    int beg = S->E[qb], end = S->E[qb+1];
    float cnt = (float)(NN - end);
    float sum = S->SS[NB] - S->SS[qb+1];
    for (int k = beg; k < end; k++) {
        float v = S->sc[k];
        if (v > q) { cnt += 1.0f; sum += v; }
    }
    float self = fmaxf(a + cself, 0.0f);
    return (a * cnt + sum - self) * scale;
}

// ---------------------------------------------------------------------------
// Fused kernel: phase1 (h1 columns + out zeroing) -> grid_sync ->
//               phase2 (h2 columns, direct atomic-accumulated output)
// ---------------------------------------------------------------------------
__global__ __launch_bounds__(NTH) void fused_all(
    const float* __restrict__ x,
    const float* __restrict__ W1,
    const float* __restrict__ b1,
    const float* __restrict__ W2,
    const float* __restrict__ b2,
    const float* __restrict__ W3,
    const float* __restrict__ b3,
    float* __restrict__ out)
{
    __shared__ RankSmem S;
    __shared__ float wt[F1], wb[F1];

    int t = threadIdx.x;
    int blk = blockIdx.x;

    // ---------------- Phase 1 ----------------
    if (blk < BB*F1) {
        int b = blk >> 5;
        int f = blk & 31;
        float w0 = W1[0*F1+f], w1 = W1[1*F1+f], w2 = W1[2*F1+f];
        float w3 = W1[3*F1+f], w4 = W1[4*F1+f], w5 = W1[5*F1+f];
        float bias = b1[f];
        const float* xb = x + b*NN*DD;

        float x0 = xb[3*t+0], x1 = xb[3*t+1], x2 = xb[3*t+2];
        float a0 = x0*w0 + x1*w1 + x2*w2 + bias;
        float c0 = x0*w3 + x1*w4 + x2*w5;
        int p = t + 512;
        x0 = xb[3*p+0]; x1 = xb[3*p+1]; x2 = xb[3*p+2];
        float a1 = x0*w0 + x1*w1 + x2*w2 + bias;
        float c1 = x0*w3 + x1*w4 + x2*w5;

        float mn, invw;
        rank_build(&S, c0, c1, t, mn, invw);

        // point-major stores
        g_h1[(b*NN + t)*F1 + f]       = rank_query(&S, a0, c0, mn, invw);
        g_h1[(b*NN + t + 512)*F1 + f] = rank_query(&S, a1, c1, mn, invw);
    } else {
        // blocks 64..127: zero the output (poisoned by harness each run)
        int idx = (blk - BB*F1)*NTH + t;
        if (idx < BB*NN*DD) out[idx] = 0.0f;
    }

    grid_sync();

    // ---------------- Phase 2: all 128 blocks, column (b, f2) ----------------
    {
        int b = blk >> 6;
        int f2 = blk & 63;
        if (t < F1) {
            wt[t] = W2[t*F2 + f2];
            wb[t] = W2[(F1 + t)*F2 + f2];
        }
        float bias = b2[f2];
        __syncthreads();

        const float* h1b = g_h1 + (size_t)b*NN*F1;
        float a0 = bias, c0 = 0.0f, a1 = bias, c1 = 0.0f;
#pragma unroll
        for (int k = 0; k < 8; k++) {
            float4 v0 = ldcg4(h1b + (size_t)t*F1 + 4*k);
            a0 += v0.x*wt[4*k+0] + v0.y*wt[4*k+1] + v0.z*wt[4*k+2] + v0.w*wt[4*k+3];
            c0 += v0.x*wb[4*k+0] + v0.y*wb[4*k+1] + v0.z*wb[4*k+2] + v0.w*wb[4*k+3];
        }
#pragma unroll
        for (int k = 0; k < 8; k++) {
            float4 v1 = ldcg4(h1b + (size_t)(t + 512)*F1 + 4*k);
            a1 += v1.x*wt[4*k+0] + v1.y*wt[4*k+1] + v1.z*wt[4*k+2] + v1.w*wt[4*k+3];
            c1 += v1.x*wb[4*k+0] + v1.y*wb[4*k+1] + v1.z*wb[4*k+2] + v1.w*wb[4*k+3];
        }

        float mn, invw;
        rank_build(&S, c0, c1, t, mn, invw);

        float h0 = rank_query(&S, a0, c0, mn, invw);
        float h1 = rank_query(&S, a1, c1, mn, invw);

        // block reduce Hsum_f2 = sum_i h2[i]
        float hloc = h0 + h1;
        __syncthreads();                       // protect redA reuse
        int lane = t & 31, w = t >> 5;
#pragma unroll
        for (int o = 16; o > 0; o >>= 1)
            hloc += __shfl_xor_sync(0xffffffffu, hloc, o);
        if (lane == 0) S.redA[w] = hloc;
        __syncthreads();
        if (t < 16) {
            float v = S.redA[t];
#pragma unroll
            for (int o = 8; o > 0; o >>= 1)
                v += __shfl_xor_sync(0x0000ffffu, v, o);
            if (t == 0) S.redA[0] = v;
        }
        __syncthreads();
        float Hsum = S.redA[0];

        // Direct output accumulation (64 blocks contribute per output point):
        // out[i,d] += h2[i]*(Wt[f2,d] - Wb[f2,d]*inv) + Hsum*Wb[f2,d]*inv + b3[d]/64
        const float inv = 1.0f / (float)(NN - 1);
        float coef[DD], addc[DD];
#pragma unroll
        for (int d = 0; d < DD; d++) {
            float wtd = W3[f2*DD + d];
            float wbd = W3[(F2 + f2)*DD + d];
            coef[d] = wtd - wbd*inv;
            addc[d] = Hsum*wbd*inv + b3[d]*(1.0f/(float)F2);  // F2=64 blocks per batch
        }
        float* o0 = out + ((size_t)b*NN + t)*DD;
        float* o1 = out + ((size_t)b*NN + t + 512)*DD;
#pragma unroll
        for (int d = 0; d < DD; d++) {
            atomicAdd(o0 + d, h0*coef[d] + addc[d]);
            atomicAdd(o1 + d, h1*coef[d] + addc[d]);
        }
    }
}

// ---------------------------------------------------------------------------
extern "C" void kernel_launch(void* const* d_in, const int* in_sizes, int n_in,
                              void* d_out, int out_size)
{
    const float* x  = (const float*)d_in[0];   // (2, 3072)
    const float* W1 = (const float*)d_in[1];   // (6, 32)
    const float* b1 = (const float*)d_in[2];   // (32,)
    const float* W2 = (const float*)d_in[3];   // (64, 64)
    const float* b2 = (const float*)d_in[4];   // (64,)
    const float* W3 = (const float*)d_in[5];   // (128, 3)
    const float* b3 = (const float*)d_in[6];   // (3,)
    float* out = (float*)d_out;

    fused_all<<<GRID, NTH>>>(x, W1, b1, W2, b2, W3, b3, out);
}

// round 13
// speedup vs baseline: 1.6616x; 1.4892x over previous
#include <cuda_runtime.h>

#define BB 2
#define NN 1024
#define DD 3
#define F1 32
#define F2 64
#define NTH 512
#define NB 256

// Scratch (no allocs allowed). g_h1 feature-major: [batch][feature][point]
__device__ float g_h1[BB*F1*NN];

// ---------------------------------------------------------------------------
// Rank-query engine (validated in R5): cnt/sum of {c_j > q} via 256-bin
// counting histogram + bucket scan. Ties contribute a + c == 0 -> free.
// ---------------------------------------------------------------------------
struct RankSmem {
    int   cnt[NB];
    int   cur[NB];
    float bsum[NB];
    int   E[NB+1];
    float SS[NB+1];
    float sc[NN];
    float redA[16];
    float redB[16];
};

__device__ void rank_build(RankSmem* S, float c0, float c1,
                           int t, float& mn_out, float& invw_out)
{
    int lane = t & 31, w = t >> 5;

    if (t < NB) { S->cnt[t] = 0; S->bsum[t] = 0.0f; }

    // block min/max of c
    float mnl = fminf(c0, c1), mxl = fmaxf(c0, c1);
#pragma unroll
    for (int o = 16; o > 0; o >>= 1) {
        mnl = fminf(mnl, __shfl_xor_sync(0xffffffffu, mnl, o));
        mxl = fmaxf(mxl, __shfl_xor_sync(0xffffffffu, mxl, o));
    }
    if (lane == 0) { S->redA[w] = mnl; S->redB[w] = mxl; }
    __syncthreads();
    if (t < 16) {
        mnl = S->redA[t]; mxl = S->redB[t];
#pragma unroll
        for (int o = 8; o > 0; o >>= 1) {
            mnl = fminf(mnl, __shfl_xor_sync(0x0000ffffu, mnl, o));
            mxl = fmaxf(mxl, __shfl_xor_sync(0x0000ffffu, mxl, o));
        }
        if (t == 0) { S->redA[0] = mnl; S->redB[0] = (float)NB / fmaxf(mxl - mnl, 1e-30f); }
    }
    __syncthreads();
    float mn = S->redA[0], invw = S->redB[0];
    mn_out = mn; invw_out = invw;

    int b0 = min(max((int)((c0 - mn) * invw), 0), NB-1);
    int b1 = min(max((int)((c1 - mn) * invw), 0), NB-1);
    atomicAdd(&S->cnt[b0], 1);  atomicAdd(&S->bsum[b0], c0);
    atomicAdd(&S->cnt[b1], 1);  atomicAdd(&S->bsum[b1], c1);
    __syncthreads();

    // exclusive scan over NB bins (count + sum), warps 0..7
    int v = 0; float s = 0.0f;
    int vi = 0; float si = 0.0f;
    if (t < NB) {
        v = S->cnt[t]; s = S->bsum[t];
        vi = v; si = s;
#pragma unroll
        for (int o = 1; o < 32; o <<= 1) {
            int   nv = __shfl_up_sync(0xffffffffu, vi, o);
            float ns = __shfl_up_sync(0xffffffffu, si, o);
            if (lane >= o) { vi += nv; si += ns; }
        }
        if (lane == 31) { S->redA[w] = (float)vi; S->redB[w] = si; }
    }
    __syncthreads();
    if (t < 8) {
        float v8 = S->redA[t], s8 = S->redB[t];
        float vv = v8, ss = s8;
#pragma unroll
        for (int o = 1; o < 8; o <<= 1) {
            float nv = __shfl_up_sync(0x000000ffu, vv, o);
            float ns = __shfl_up_sync(0x000000ffu, ss, o);
            if (t >= o) { vv += nv; ss += ns; }
        }
        S->redA[t] = vv - v8;
        S->redB[t] = ss - s8;
    }
    __syncthreads();
    if (t < NB) {
        int   excl  = vi - v + (int)S->redA[w];
        float exclS = si - s + S->redB[w];
        S->E[t] = excl; S->SS[t] = exclS; S->cur[t] = excl;
        if (t == NB-1) { S->E[NB] = excl + v; S->SS[NB] = exclS + s; }
    }
    __syncthreads();

    int p0 = atomicAdd(&S->cur[b0], 1);  S->sc[p0] = c0;
    int p1 = atomicAdd(&S->cur[b1], 1);  S->sc[p1] = c1;
    __syncthreads();
}

__device__ __forceinline__ float rank_query(const RankSmem* S, float a, float cself,
                                            float mn, float invw)
{
    const float scale = 1.0f / (float)(NN - 1);
    float q = -a;
    int qb = min(max((int)((q - mn) * invw), 0), NB-1);
    int beg = S->E[qb], end = S->E[qb+1];
    float cnt = (float)(NN - end);
    float sum = S->SS[NB] - S->SS[qb+1];
    for (int k = beg; k < end; k++) {
        float v = S->sc[k];
        if (v > q) { cnt += 1.0f; sum += v; }
    }
    float self = fmaxf(a + cself, 0.0f);
    return (a * cnt + sum - self) * scale;
}

// ---------------------------------------------------------------------------
// Stage 1: one block per (batch, feature f of 32). Writes h1 column.
// Also zeroes the output buffer (read by stage2's atomics; stream-ordered).
// ---------------------------------------------------------------------------
__global__ __launch_bounds__(NTH) void stage1(
    const float* __restrict__ x,
    const float* __restrict__ W1,
    const float* __restrict__ b1,
    float* __restrict__ out)
{
    __shared__ RankSmem S;

    int t = threadIdx.x;

    // zero output (64 blocks x 512 threads >= 6144 elements)
    int zi = blockIdx.x * NTH + t;
    if (zi < BB*NN*DD) out[zi] = 0.0f;

    int b = blockIdx.x >> 5;
    int f = blockIdx.x & 31;

    float w0 = W1[0*F1+f], w1 = W1[1*F1+f], w2 = W1[2*F1+f];
    float w3 = W1[3*F1+f], w4 = W1[4*F1+f], w5 = W1[5*F1+f];
    float bias = b1[f];
    const float* xb = x + b*NN*DD;

    float a0, a1, c0, c1;
    {
        float x0 = xb[3*t+0], x1 = xb[3*t+1], x2 = xb[3*t+2];
        a0 = x0*w0 + x1*w1 + x2*w2 + bias;
        c0 = x0*w3 + x1*w4 + x2*w5;
        int p = t + 512;
        x0 = xb[3*p+0]; x1 = xb[3*p+1]; x2 = xb[3*p+2];
        a1 = x0*w0 + x1*w1 + x2*w2 + bias;
        c1 = x0*w3 + x1*w4 + x2*w5;
    }

    float mn, invw;
    rank_build(&S, c0, c1, t, mn, invw);

    float* hout = g_h1 + (b*F1 + f)*NN;
    hout[t]       = rank_query(&S, a0, c0, mn, invw);
    hout[t + 512] = rank_query(&S, a1, c1, mn, invw);
}

// ---------------------------------------------------------------------------
// Stage 2 (fused with block-3 closed form): one block per (batch, f2 of 64).
// Computes the h2 column, its sum, and commits this column's additive
// contribution to the output directly:
//   out[i,d] += h2[i]*(Wt[f2,d] - Wb[f2,d]*inv) + Hsum*Wb[f2,d]*inv + b3[d]/F2
// (validated in R11 with the 1/F2 bias shard)
// ---------------------------------------------------------------------------
__global__ __launch_bounds__(NTH) void stage2_fused(
    const float* __restrict__ W2,
    const float* __restrict__ b2,
    const float* __restrict__ W3,
    const float* __restrict__ b3,
    float* __restrict__ out)
{
    __shared__ RankSmem S;
    __shared__ float wt[F1], wb[F1];

    int t = threadIdx.x;
    int b = blockIdx.x >> 6;
    int f2 = blockIdx.x & 63;

    if (t < F1) {
        wt[t] = W2[t*F2 + f2];
        wb[t] = W2[(F1 + t)*F2 + f2];
    }
    float bias = b2[f2];
    __syncthreads();

    const float* h1b = g_h1 + b*F1*NN;
    float a0 = bias, c0 = 0.0f, a1 = bias, c1 = 0.0f;
#pragma unroll
    for (int f = 0; f < F1; f++) {
        float hv0 = __ldg(&h1b[f*NN + t]);          // cross-kernel data: safe
        float hv1 = __ldg(&h1b[f*NN + t + 512]);
        a0 += hv0 * wt[f];  c0 += hv0 * wb[f];
        a1 += hv1 * wt[f];  c1 += hv1 * wb[f];
    }

    float mn, invw;
    rank_build(&S, c0, c1, t, mn, invw);

    float h0 = rank_query(&S, a0, c0, mn, invw);
    float h1 = rank_query(&S, a1, c1, mn, invw);

    // block-reduce Hsum = sum_i h2[i]
    float hloc = h0 + h1;
    __syncthreads();
    int lane = t & 31, w = t >> 5;
#pragma unroll
    for (int o = 16; o > 0; o >>= 1)
        hloc += __shfl_xor_sync(0xffffffffu, hloc, o);
    if (lane == 0) S.redA[w] = hloc;
    __syncthreads();
    if (t < 16) {
        float v = S.redA[t];
#pragma unroll
        for (int o = 8; o > 0; o >>= 1)
            v += __shfl_xor_sync(0x0000ffffu, v, o);
        if (t == 0) S.redA[0] = v;
    }
    __syncthreads();
    float Hsum = S.redA[0];

    // direct output commit (F2=64 blocks contribute per output point)
    const float inv = 1.0f / (float)(NN - 1);
    float coef[DD], addc[DD];
#pragma unroll
    for (int d = 0; d < DD; d++) {
        float wtd = W3[f2*DD + d];
        float wbd = W3[(F2 + f2)*DD + d];
        coef[d] = wtd - wbd*inv;
        addc[d] = Hsum*wbd*inv + b3[d]*(1.0f/(float)F2);
    }
    float* o0 = out + ((size_t)b*NN + t)*DD;
    float* o1 = out + ((size_t)b*NN + t + 512)*DD;
#pragma unroll
    for (int d = 0; d < DD; d++) {
        atomicAdd(o0 + d, h0*coef[d] + addc[d]);
        atomicAdd(o1 + d, h1*coef[d] + addc[d]);
    }
}

// ---------------------------------------------------------------------------
extern "C" void kernel_launch(void* const* d_in, const int* in_sizes, int n_in,
                              void* d_out, int out_size)
{
    const float* x  = (const float*)d_in[0];   // (2, 3072)
    const float* W1 = (const float*)d_in[1];   // (6, 32)
    const float* b1 = (const float*)d_in[2];   // (32,)
    const float* W2 = (const float*)d_in[3];   // (64, 64)
    const float* b2 = (const float*)d_in[4];   // (64,)
    const float* W3 = (const float*)d_in[5];   // (128, 3)
    const float* b3 = (const float*)d_in[6];   // (3,)
    float* out = (float*)d_out;

    stage1<<<BB*F1, NTH>>>(x, W1, b1, out);              // 64 blocks
    stage2_fused<<<BB*F2, NTH>>>(W2, b2, W3, b3, out);   // 128 blocks
}